// round 16
// baseline (speedup 1.0000x reference)
#include <cuda_runtime.h>
#include <cuda_bf16.h>
#include <stdint.h>
#include <math.h>

#define BB   16
#define TT   8000
#define TN   800
#define HID  512
#define LAT  128
#define KCB  1024
#define NQ   4
#define COUNT_DEC 1599
#define NCHUNKS   25584   // BB * COUNT_DEC
#define RESCORE_TAU 4e-3f
#define TAU1 0.15f

// ---------------- scratch (device globals; no allocation allowed) ----------------
__device__ float g_z1[BB*HID*TN];        // enc1 out (B,512,800)
__device__ float g_z3[(size_t)BB*HID*TT];// enc2a out (B,512,8000)
__device__ float g_ze[(size_t)BB*TT*LAT];// enc2b out, transposed (B,T,128)
__device__ float g_res[(size_t)BB*TT*LAT];
__device__ float g_qout[(size_t)BB*TT*LAT];
__device__ int   g_codes[BB*TT*NQ];
__device__ float g_cbn[NQ*KCB];
__device__ float g_w1t[132*5*512];       // dec1 weights transposed
__device__ float g_w2t[512*3*128];       // dec2 weights transposed
__device__ float g_wb[1*64*8*7*132];     // enc2b weights pre-staged (scalar conv3)
// enc2a HMMA weight image: per (ocb,chunk): [limb(2)][oc(128)][kpad(88)] bf16
__device__ __nv_bfloat16 g_wh[4*32*22528];
// codebook limb images: [(qi*8+cc)][limb(2)][code(128)][kp(132)] bf16
__device__ __nv_bfloat16 g_cbl[4*8*2*128*132];
__device__ double g_acc[8];  // [0..3] vq sums, [4] smooth count, [5] recon sum

__device__ __forceinline__ uint32_t pkbf(__nv_bfloat16 x, __nv_bfloat16 y) {
    return (uint32_t)__bfloat16_as_ushort(x) | ((uint32_t)__bfloat16_as_ushort(y) << 16);
}

#define MMA16816(C, A, B0, B1) \
    asm volatile("mma.sync.aligned.m16n8k16.row.col.f32.bf16.bf16.f32 " \
        "{%0,%1,%2,%3}, {%4,%5,%6,%7}, {%8,%9}, {%0,%1,%2,%3};" \
        : "+f"((C)[0]), "+f"((C)[1]), "+f"((C)[2]), "+f"((C)[3]) \
        : "r"((A)[0]), "r"((A)[1]), "r"((A)[2]), "r"((A)[3]), "r"(B0), "r"(B1))

// ---------------- tiny utility kernels ----------------
__global__ void k_zero_acc() {
    if (threadIdx.x < 8) g_acc[threadIdx.x] = 0.0;
}
__global__ void k_tw1(const float* __restrict__ w1) {
    int idx = blockIdx.x * 256 + threadIdx.x;
    if (idx >= 512*660) return;
    int o = idx / 660, r = idx % 660;
    g_w1t[r*512 + o] = w1[idx];
}
__global__ void k_tw2(const float* __restrict__ w2) {
    int idx = blockIdx.x * 256 + threadIdx.x;
    if (idx >= 128*1536) return;
    int o = idx / 1536, r = idx % 1536;
    g_w2t[r*128 + o] = w2[idx];
}
__global__ void k_wstage(const float* __restrict__ wt, float* __restrict__ dst,
                         int K, int OCB) {
    int idx = blockIdx.x * 256 + threadIdx.x;
    int total = OCB * 64 * 8 * K * 128;
    if (idx >= total) return;
    int ol = idx & 127;
    int r  = idx >> 7;
    int j  = r % K;  r /= K;
    int i  = r & 7;  r >>= 3;
    int chunk = r & 63;
    int ocb   = r >> 6;
    dst[((size_t)(ocb*64 + chunk))*(8*K*132) + (i*K + j)*132 + ol] =
        wt[((size_t)(ocb*128 + ol)*512 + chunk*8 + i)*K + j];
}

// enc2a weight prep: im2col k = icl*5 + j (icl in 16-ic chunk), 2 bf16 limbs
__global__ void k_wprep2(const float* __restrict__ wt) {
    int idx = blockIdx.x * 256 + threadIdx.x;
    if (idx >= 4*32*128*88) return;
    int kp = idx % 88; int r = idx / 88;
    int oc = r % 128; r /= 128;
    int ch = r % 32; int ocb = r / 32;
    float w = 0.f;
    if (kp < 80) {
        int icl = kp / 5, j = kp - icl*5;
        w = wt[(((size_t)(ocb*128 + oc))*512 + ch*16 + icl)*5 + j];
    }
    __nv_bfloat16 h = __float2bfloat16(w);
    __nv_bfloat16 l = __float2bfloat16(w - __bfloat162float(h));
    size_t base = (size_t)(ocb*32 + ch)*22528 + (size_t)oc*88 + kp;
    g_wh[base] = h;
    g_wh[base + 11264] = l;
}

// codebook 2-limb prep
__global__ void k_cbprep(const float* __restrict__ cb) {
    int idx = blockIdx.x * 256 + threadIdx.x;
    if (idx >= 4*8*128*132) return;
    int kp = idx % 132; int r = idx / 132;
    int code = r % 128; r /= 128;
    int cc = r % 8; int qi = r / 8;
    float v = 0.f;
    if (kp < 128) v = cb[((size_t)(qi*KCB + cc*128 + code))*LAT + kp];
    __nv_bfloat16 h = __float2bfloat16(v);
    __nv_bfloat16 m = __float2bfloat16(v - __bfloat162float(h));
    size_t base = ((size_t)((qi*8 + cc)*2)*128 + code)*132 + kp;
    g_cbl[base] = h;
    g_cbl[base + 128*132] = m;
}

// ---------------- enc1: (B,20,800) -> relu conv K=3 -> (B,512,800) ----------------
__global__ __launch_bounds__(256) void k_enc1(const float* __restrict__ traj,
                                              const float* __restrict__ w,
                                              const float* __restrict__ bias) {
    __shared__ float xs[20][18];
    int b = blockIdx.y, t0 = blockIdx.x * 16;
    int tid = threadIdx.x;
    for (int e = tid; e < 20*18; e += 256) {
        int i = e / 18, u = e % 18;
        int tg = t0 + u - 1;
        float v = 0.f;
        if (tg >= 0 && tg < TN) v = traj[((size_t)b*2 + (i/10))*TT + tg*10 + (i%10)];
        xs[i][u] = v;
    }
    __syncthreads();
    int o0 = tid, o1 = tid + 256;
    float acc0[16], acc1[16];
    float b0 = bias[o0], b1v = bias[o1];
    #pragma unroll
    for (int t = 0; t < 16; t++) { acc0[t] = 0.f; acc1[t] = 0.f; }
    for (int i = 0; i < 20; i++) {
        #pragma unroll
        for (int j = 0; j < 3; j++) {
            float w0 = w[(o0*20 + i)*3 + j];
            float w1 = w[(o1*20 + i)*3 + j];
            #pragma unroll
            for (int t = 0; t < 16; t++) {
                float x = xs[i][t + j];
                acc0[t] += w0 * x;
                acc1[t] += w1 * x;
            }
        }
    }
    #pragma unroll
    for (int t = 0; t < 16; t++) {
        g_z1[((size_t)b*HID + o0)*TN + t0 + t] = fmaxf(acc0[t] + b0, 0.f);
        g_z1[((size_t)b*HID + o1)*TN + t0 + t] = fmaxf(acc1[t] + b1v, 0.f);
    }
}

// ---------------- enc2a via mma.sync bf16 2-limb (HMMA) ----------------
__global__ __launch_bounds__(256) void k_enc2a_hmma(
    const __nv_bfloat16* __restrict__ wh, const float* __restrict__ bias) {
    extern __shared__ char smem[];
    __nv_bfloat16* ash = (__nv_bfloat16*)smem;          // [2][128][88] bf16
    float* zr = (float*)(smem + 45056);                 // [16][68] f32
    int tid = threadIdx.x, lane = tid & 31, warp = tid >> 5;
    int wm = warp & 3, wn = warp >> 2;
    int t0 = blockIdx.x * 64, ob = blockIdx.y * 128, b = blockIdx.z;

    float c[2][4][4];
    #pragma unroll
    for (int i = 0; i < 2; i++)
        #pragma unroll
        for (int nt = 0; nt < 4; nt++)
            #pragma unroll
            for (int q = 0; q < 4; q++) c[i][nt][q] = 0.f;

    uint32_t adst = (uint32_t)__cvta_generic_to_shared(ash);

    for (int ch = 0; ch < 32; ch++) {
        __syncthreads();
        {
            const __nv_bfloat16* src = wh + (size_t)(blockIdx.y*32 + ch) * 22528;
            #pragma unroll
            for (int it = 0; it < 11; it++) {
                int e = tid + it*256;
                asm volatile("cp.async.ca.shared.global [%0], [%1], 16;"
                             :: "r"(adst + e*16), "l"((const void*)(src + e*8)));
            }
            asm volatile("cp.async.commit_group;");
        }
        {
            int ic0 = ch * 16;
            for (int e = tid; e < 1088; e += 256) {
                int icl = e / 68, u = e - icl*68;
                int tg = t0 + u - 2;
                float v = 0.f;
                if (tg >= 0 && tg < TT) {
                    const float* row = g_z1 + ((size_t)b*HID + ic0 + icl)*TN;
                    float srcp = fmaxf(((float)tg + 0.5f)*0.5f - 0.5f, 0.0f);
                    int i0 = (int)srcp;
                    int i1 = min(i0 + 1, 3999);
                    float frac = srcp - (float)i0;
                    v = row[i0/5]*(1.0f - frac) + row[i1/5]*frac;
                }
                zr[e] = v;
            }
        }
        asm volatile("cp.async.wait_group 0;");
        __syncthreads();

        #pragma unroll
        for (int ks = 0; ks < 5; ks++) {
            int kb = ks*16 + (lane & 3)*2;
            uint32_t bL1[4][2], bL2[4][2];
            #pragma unroll
            for (int nt = 0; nt < 4; nt++) {
                int n = wn*32 + nt*8 + (lane >> 2);
                float zv[4];
                #pragma unroll
                for (int q = 0; q < 4; q++) {
                    int kl = kb + (q & 1) + ((q & 2) ? 8 : 0);
                    int icl = kl / 5, j = kl - icl*5;
                    zv[q] = zr[icl*68 + n + j];
                }
                __nv_bfloat16 h[4], l[4];
                #pragma unroll
                for (int q = 0; q < 4; q++) {
                    h[q] = __float2bfloat16(zv[q]);
                    l[q] = __float2bfloat16(zv[q] - __bfloat162float(h[q]));
                }
                bL1[nt][0] = pkbf(h[0], h[1]); bL1[nt][1] = pkbf(h[2], h[3]);
                bL2[nt][0] = pkbf(l[0], l[1]); bL2[nt][1] = pkbf(l[2], l[3]);
            }
            uint32_t aF[2][2][4];
            #pragma unroll
            for (int i = 0; i < 2; i++) {
                int m = wm*32 + i*16 + (lane >> 2);
                #pragma unroll
                for (int lb = 0; lb < 2; lb++) {
                    const __nv_bfloat16* base = ash + lb*11264;
                    aF[i][lb][0] = *(const uint32_t*)(base + (size_t)m*88 + kb);
                    aF[i][lb][1] = *(const uint32_t*)(base + (size_t)(m + 8)*88 + kb);
                    aF[i][lb][2] = *(const uint32_t*)(base + (size_t)m*88 + kb + 8);
                    aF[i][lb][3] = *(const uint32_t*)(base + (size_t)(m + 8)*88 + kb + 8);
                }
            }
            #pragma unroll
            for (int i = 0; i < 2; i++) {
                #pragma unroll
                for (int nt = 0; nt < 4; nt++) {
                    MMA16816(c[i][nt], aF[i][0], bL1[nt][0], bL1[nt][1]);
                    MMA16816(c[i][nt], aF[i][0], bL2[nt][0], bL2[nt][1]);
                    MMA16816(c[i][nt], aF[i][1], bL1[nt][0], bL1[nt][1]);
                }
            }
        }
    }

    #pragma unroll
    for (int i = 0; i < 2; i++) {
        int oc0 = ob + wm*32 + i*16 + (lane >> 2);
        float bv0 = bias[oc0], bv1 = bias[oc0 + 8];
        #pragma unroll
        for (int nt = 0; nt < 4; nt++) {
            int t = t0 + wn*32 + nt*8 + (lane & 3)*2;
            float2 v0, v1;
            v0.x = fmaxf(c[i][nt][0] + bv0, 0.f);
            v0.y = fmaxf(c[i][nt][1] + bv0, 0.f);
            v1.x = fmaxf(c[i][nt][2] + bv1, 0.f);
            v1.y = fmaxf(c[i][nt][3] + bv1, 0.f);
            *(float2*)&g_z3[((size_t)b*HID + oc0)*TT + t]     = v0;
            *(float2*)&g_z3[((size_t)b*HID + oc0 + 8)*TT + t] = v1;
        }
    }
}

// ---------------- conv3 scalar path (enc2b), from R11 ----------------
template<int K, bool RELU, bool TROUT, bool INTERP, int OCB>
__global__ __launch_bounds__(256) void k_conv3(const float* __restrict__ in,
                                               const float* __restrict__ ws,
                                               const float* __restrict__ bias,
                                               float* __restrict__ out) {
    constexpr int P   = (K - 1) / 2;
    constexpr int ZW  = 32 + K - 1;
    constexpr int ZWP = (ZW + 3) & ~3;
    constexpr int WB  = 8 * K * 132;
    constexpr int WB4 = WB / 4;
    constexpr int WITER = (WB4 + 255) / 256;
    constexpr int NZ4 = (K + 6) / 4;
    extern __shared__ float smemf[];
    float* wbuf0 = smemf;
    float* wbuf1 = smemf + WB;
    float* zbuf0 = smemf + 2*WB;
    float* zbuf1 = smemf + 2*WB + 8*ZWP;

    int tid = threadIdx.x;
    int tx = tid & 7, ty = tid >> 3;
    int t0 = blockIdx.x * 32, ob = blockIdx.y * 128, b = blockIdx.z;
    int OCt = OCB * 128;
    int o = ob + ty*4, tt = tx*4;

    float acc[4][4], sum[4][4];
    #pragma unroll
    for (int cIdx = 0; cIdx < 4; cIdx++)
        #pragma unroll
        for (int tl = 0; tl < 4; tl++) { acc[cIdx][tl] = 0.f; sum[cIdx][tl] = 0.f; }

    float zt[2];
    {
        const float* src = ws + ((size_t)(blockIdx.y*64 + 0))*WB;
        uint32_t dst = (uint32_t)__cvta_generic_to_shared(wbuf0);
        #pragma unroll
        for (int it = 0; it < WITER; it++) {
            int e = tid + it*256;
            if (e < WB4)
                asm volatile("cp.async.ca.shared.global [%0], [%1], 16;"
                             :: "r"(dst + e*16), "l"((const void*)(src + e*4)));
        }
        asm volatile("cp.async.commit_group;");
        #pragma unroll
        for (int k = 0; k < 2; k++) {
            int e = tid + k*256;
            float v = 0.f;
            if (e < 8*ZW) {
                int i = e / ZW, u = e - i*ZW;
                int tg = t0 + u - P;
                if (tg >= 0 && tg < TT) {
                    if (INTERP) {
                        const float* row = g_z1 + ((size_t)b*HID + i)*TN;
                        float srcp = fmaxf(((float)tg + 0.5f)*0.5f - 0.5f, 0.0f);
                        int i0 = (int)srcp;
                        int i1 = min(i0 + 1, 3999);
                        float frac = srcp - (float)i0;
                        v = row[i0/5] * (1.0f - frac) + row[i1/5] * frac;
                    } else {
                        v = in[((size_t)b*HID + i)*TT + tg];
                    }
                }
            }
            zt[k] = v;
        }
        asm volatile("cp.async.wait_group 0;");
        #pragma unroll
        for (int k = 0; k < 2; k++) {
            int e = tid + k*256;
            if (e < 8*ZW) { int i = e / ZW, u = e - i*ZW; zbuf0[i*ZWP + u] = zt[k]; }
        }
        __syncthreads();
    }

    for (int c = 0; c < 64; c++) {
        const float* wb_ = (c & 1) ? wbuf1 : wbuf0;
        const float* zb_ = (c & 1) ? zbuf1 : zbuf0;
        float* wbn = (c & 1) ? wbuf0 : wbuf1;
        float* zbn = (c & 1) ? zbuf0 : zbuf1;
        if (c < 63) {
            const float* src = ws + ((size_t)(blockIdx.y*64 + c + 1))*WB;
            uint32_t dst = (uint32_t)__cvta_generic_to_shared(wbn);
            #pragma unroll
            for (int it = 0; it < WITER; it++) {
                int e = tid + it*256;
                if (e < WB4)
                    asm volatile("cp.async.ca.shared.global [%0], [%1], 16;"
                                 :: "r"(dst + e*16), "l"((const void*)(src + e*4)));
            }
            asm volatile("cp.async.commit_group;");
            int ic0 = (c + 1) * 8;
            #pragma unroll
            for (int k = 0; k < 2; k++) {
                int e = tid + k*256;
                float v = 0.f;
                if (e < 8*ZW) {
                    int i = e / ZW, u = e - i*ZW;
                    int tg = t0 + u - P;
                    if (tg >= 0 && tg < TT) {
                        if (INTERP) {
                            const float* row = g_z1 + ((size_t)b*HID + ic0 + i)*TN;
                            float srcp = fmaxf(((float)tg + 0.5f)*0.5f - 0.5f, 0.0f);
                            int i0 = (int)srcp;
                            int i1 = min(i0 + 1, 3999);
                            float frac = srcp - (float)i0;
                            v = row[i0/5] * (1.0f - frac) + row[i1/5] * frac;
                        } else {
                            v = in[((size_t)b*HID + ic0 + i)*TT + tg];
                        }
                    }
                }
                zt[k] = v;
            }
        }
        #pragma unroll
        for (int i = 0; i < 8; i++) {
            float zl[NZ4 * 4];
            #pragma unroll
            for (int q = 0; q < NZ4; q++)
                *(float4*)&zl[q*4] = *(const float4*)&zb_[i*ZWP + tt + q*4];
            #pragma unroll
            for (int j = 0; j < K; j++) {
                float4 wv = *(const float4*)&wb_[(i*K + j)*132 + ty*4];
                #pragma unroll
                for (int tl = 0; tl < 4; tl++) {
                    float z = zl[tl + j];
                    acc[0][tl] += wv.x * z;
                    acc[1][tl] += wv.y * z;
                    acc[2][tl] += wv.z * z;
                    acc[3][tl] += wv.w * z;
                }
            }
        }
        if ((c & 3) == 3) {
            #pragma unroll
            for (int cIdx = 0; cIdx < 4; cIdx++)
                #pragma unroll
                for (int tl = 0; tl < 4; tl++) { sum[cIdx][tl] += acc[cIdx][tl]; acc[cIdx][tl] = 0.f; }
        }
        if (c < 63) {
            asm volatile("cp.async.wait_group 0;");
            #pragma unroll
            for (int k = 0; k < 2; k++) {
                int e = tid + k*256;
                if (e < 8*ZW) { int i = e / ZW, u = e - i*ZW; zbn[i*ZWP + u] = zt[k]; }
            }
        }
        __syncthreads();
    }

    float resv[4][4];
    #pragma unroll
    for (int cIdx = 0; cIdx < 4; cIdx++) {
        float bv = bias[o + cIdx];
        #pragma unroll
        for (int tl = 0; tl < 4; tl++) {
            float v = sum[cIdx][tl] + bv;
            if (RELU) v = fmaxf(v, 0.f);
            resv[cIdx][tl] = v;
        }
    }
    if (!TROUT) {
        #pragma unroll
        for (int cIdx = 0; cIdx < 4; cIdx++) {
            float4 v = make_float4(resv[cIdx][0], resv[cIdx][1], resv[cIdx][2], resv[cIdx][3]);
            *(float4*)&out[((size_t)b*OCt + o + cIdx)*TT + t0 + tt] = v;
        }
    } else {
        #pragma unroll
        for (int tl = 0; tl < 4; tl++) {
            float4 v = make_float4(resv[0][tl], resv[1][tl], resv[2][tl], resv[3][tl]);
            *(float4*)&out[((size_t)b*TT + t0 + tt + tl)*OCt + o] = v;
        }
    }
}

// ---------------- codebook squared norms ----------------
__global__ void k_cbnorm(const float* __restrict__ cb) {
    int id = blockIdx.x * 256 + threadIdx.x;
    if (id >= NQ * KCB) return;
    const float* r = cb + (size_t)id * LAT;
    double s = 0.0;
    for (int d = 0; d < LAT; d++) {
        double v = (double)r[d];
        s += v * v;
    }
    g_cbn[id] = (float)s;
}

// ---------------- residual VQ: 2-limb HMMA scan + fp32 + fp64 guard tiers ---------
__global__ __launch_bounds__(256) void k_vq(const float* __restrict__ cb_all, int qi) {
    extern __shared__ char smv[];
    float* rsm = (float*)smv;                                  // 64 x 132 f32
    __nv_bfloat16* rh = (__nv_bfloat16*)(smv + 33792);         // 64 x 132
    __nv_bfloat16* rm = rh + 64*132;                           // ends 67584
    __nv_bfloat16* cbs = (__nv_bfloat16*)(smv + 67584);        // 2 x 128 x 132, ends 135168
    float* nsm = (float*)(smv + 135168);                       // 128 f32
    int tid = threadIdx.x, lane = tid & 31, w = tid >> 5;
    int row0 = blockIdx.x * 64;
    const float* src = (qi == 0) ? g_ze : g_res;
    for (int e = tid; e < 64*32; e += 256) {
        int lr = e >> 5, d4 = (e & 31) * 4;
        float4 v = *(const float4*)&src[(size_t)(row0 + lr)*LAT + d4];
        *(float4*)&rsm[lr*132 + d4] = v;
    }
    __syncthreads();
    // pre-split residual rows into 2 bf16 limb tiles
    for (int e = tid; e < 64*128; e += 256) {
        int r = e >> 7, d = e & 127;
        float v = rsm[r*132 + d];
        __nv_bfloat16 h = __float2bfloat16(v);
        __nv_bfloat16 m = __float2bfloat16(v - __bfloat162float(h));
        rh[r*132 + d] = h; rm[r*132 + d] = m;
    }

    const float* cbq = cb_all + (size_t)qi * KCB * LAT;
    const __nv_bfloat16* cblq = g_cbl + (size_t)qi * 8 * 2 * 128 * 132;
    uint32_t cdst = (uint32_t)__cvta_generic_to_shared(cbs);

    float best[2], sec[2]; int bidx[2];
    best[0] = 3.4e38f; best[1] = 3.4e38f;
    sec[0]  = 3.4e38f; sec[1]  = 3.4e38f;
    bidx[0] = 0; bidx[1] = 0;
    int nrow = w*8 + (lane >> 2);    // residual row handled by this lane's B fragment

    for (int cc = 0; cc < 8; cc++) {
        __syncthreads();   // protect cbs/nsm reuse
        {
            const __nv_bfloat16* sb = cblq + (size_t)cc * 2 * 128 * 132;
            #pragma unroll
            for (int it = 0; it < 17; it++) {
                int e = tid + it*256;
                if (e < 4224)
                    asm volatile("cp.async.ca.shared.global [%0], [%1], 16;"
                                 :: "r"(cdst + e*16), "l"((const void*)(sb + e*8)));
            }
            asm volatile("cp.async.commit_group;");
        }
        if (tid < 128) nsm[tid] = g_cbn[qi*KCB + cc*128 + tid];
        asm volatile("cp.async.wait_group 0;");
        __syncthreads();

        float C[8][4];
        #pragma unroll
        for (int mt = 0; mt < 8; mt++)
            #pragma unroll
            for (int q = 0; q < 4; q++) C[mt][q] = 0.f;

        #pragma unroll
        for (int ks = 0; ks < 8; ks++) {
            int kb = ks*16 + (lane & 3)*2;
            uint32_t b1a = *(const uint32_t*)(rh + (size_t)nrow*132 + kb);
            uint32_t b1b = *(const uint32_t*)(rh + (size_t)nrow*132 + kb + 8);
            uint32_t b2a = *(const uint32_t*)(rm + (size_t)nrow*132 + kb);
            uint32_t b2b = *(const uint32_t*)(rm + (size_t)nrow*132 + kb + 8);
            #pragma unroll
            for (int mt = 0; mt < 8; mt++) {
                int mr = mt*16 + (lane >> 2);
                uint32_t aH[4], aM[4];
                const __nv_bfloat16* bH = cbs;
                const __nv_bfloat16* bM = cbs + 128*132;
                aH[0] = *(const uint32_t*)(bH + (size_t)mr*132 + kb);
                aH[1] = *(const uint32_t*)(bH + (size_t)(mr + 8)*132 + kb);
                aH[2] = *(const uint32_t*)(bH + (size_t)mr*132 + kb + 8);
                aH[3] = *(const uint32_t*)(bH + (size_t)(mr + 8)*132 + kb + 8);
                aM[0] = *(const uint32_t*)(bM + (size_t)mr*132 + kb);
                aM[1] = *(const uint32_t*)(bM + (size_t)(mr + 8)*132 + kb);
                aM[2] = *(const uint32_t*)(bM + (size_t)mr*132 + kb + 8);
                aM[3] = *(const uint32_t*)(bM + (size_t)(mr + 8)*132 + kb + 8);
                MMA16816(C[mt], aH, b1a, b1b);
                MMA16816(C[mt], aH, b2a, b2b);
                MMA16816(C[mt], aM, b1a, b1b);
            }
        }
        // dist + in-lane best/second update (ascending code order)
        #pragma unroll
        for (int mt = 0; mt < 8; mt++) {
            int lm0 = mt*16 + (lane >> 2);
            float n0 = nsm[lm0], n1 = nsm[lm0 + 8];
            int g0 = cc*128 + lm0, g1 = g0 + 8;
            float d0 = n0 - 2.f*C[mt][0];
            float d1 = n0 - 2.f*C[mt][1];
            float d2 = n1 - 2.f*C[mt][2];
            float d3 = n1 - 2.f*C[mt][3];
            if (d0 < best[0]) { sec[0] = best[0]; best[0] = d0; bidx[0] = g0; }
            else if (d0 < sec[0]) sec[0] = d0;
            if (d1 < best[1]) { sec[1] = best[1]; best[1] = d1; bidx[1] = g0; }
            else if (d1 < sec[1]) sec[1] = d1;
            if (d2 < best[0]) { sec[0] = best[0]; best[0] = d2; bidx[0] = g1; }
            else if (d2 < sec[0]) sec[0] = d2;
            if (d3 < best[1]) { sec[1] = best[1]; best[1] = d3; bidx[1] = g1; }
            else if (d3 < sec[1]) sec[1] = d3;
        }
    }

    // cross-lane reduce (lanes sharing lane&3 hold the same n columns)
    #pragma unroll
    for (int off = 4; off <= 16; off <<= 1) {
        #pragma unroll
        for (int ec = 0; ec < 2; ec++) {
            float ob = __shfl_xor_sync(0xffffffffu, best[ec], off);
            int   oi = __shfl_xor_sync(0xffffffffu, bidx[ec], off);
            float os = __shfl_xor_sync(0xffffffffu, sec[ec], off);
            if (ob < best[ec] || (ob == best[ec] && oi < bidx[ec])) {
                sec[ec] = fminf(best[ec], os);
                best[ec] = ob; bidx[ec] = oi;
            } else {
                sec[ec] = fminf(sec[ec], ob);
            }
        }
    }

    double dq_local = 0.0;
    #pragma unroll
    for (int rr = 0; rr < 8; rr++) {
        int srcl = rr >> 1, ec = rr & 1;
        float v1 = __shfl_sync(0xffffffffu, best[ec], srcl);
        float v2 = __shfl_sync(0xffffffffu, sec[ec], srcl);
        int   i1 = __shfl_sync(0xffffffffu, bidx[ec], srcl);
        int ix = i1;
        int rloc = w*8 + rr;
        // ---- tier 2: fp32 exact rescan when the HMMA margin is small ----
        if (v2 - v1 < TAU1) {
            float bv = 3.4e38f, sv = 3.4e38f; int bI = 0x7fffffff;
            for (int kk = 0; kk < 32; kk++) {
                int k = kk*32 + lane;
                const float* cr = cbq + (size_t)k * LAT;
                float dot = 0.f;
                for (int d = 0; d < 128; d += 4) {
                    float4 cv = *(const float4*)&cr[d];
                    float4 rv2 = *(const float4*)&rsm[rloc*132 + d];
                    dot += rv2.x*cv.x + rv2.y*cv.y + rv2.z*cv.z + rv2.w*cv.w;
                }
                float dist = g_cbn[qi*KCB + k] - 2.f*dot;
                if (dist < bv || (dist == bv && k < bI)) { sv = bv; bv = dist; bI = k; }
                else if (dist < sv) sv = dist;
            }
            #pragma unroll
            for (int off = 16; off > 0; off >>= 1) {
                float ob = __shfl_xor_sync(0xffffffffu, bv, off);
                int   oi = __shfl_xor_sync(0xffffffffu, bI, off);
                float os = __shfl_xor_sync(0xffffffffu, sv, off);
                if (ob < bv || (ob == bv && oi < bI)) {
                    sv = fminf(bv, os);
                    bv = ob; bI = oi;
                } else {
                    sv = fminf(sv, ob);
                }
            }
            ix = bI;
            // ---- tier 3: exact fp64 rescore when the fp32 margin is small ----
            if (sv - bv < RESCORE_TAU) {
                double bd = 1e300; int bi = 0x7fffffff;
                for (int kk = 0; kk < 32; kk++) {
                    int k = kk*32 + lane;
                    const float* cr = cbq + (size_t)k * LAT;
                    double s = 0.0;
                    for (int d = 0; d < 128; d++) {
                        double cd = (double)cr[d];
                        double rd = (double)rsm[rloc*132 + d];
                        s += cd*cd - 2.0*rd*cd;
                    }
                    if (s < bd || (s == bd && k < bi)) { bd = s; bi = k; }
                }
                #pragma unroll
                for (int off = 16; off > 0; off >>= 1) {
                    double ob = __shfl_xor_sync(0xffffffffu, bd, off);
                    int    oi = __shfl_xor_sync(0xffffffffu, bi, off);
                    if (ob < bd || (ob == bd && oi < bi)) { bd = ob; bi = oi; }
                }
                ix = bi;
            }
        }

        int r = row0 + rloc;
        const float* q = cbq + (size_t)ix * LAT;
        float4 qv = *(const float4*)&q[lane*4];
        float4 rv = *(const float4*)&rsm[rloc*132 + lane*4];
        double r2 = (double)rv.x*rv.x + (double)rv.y*rv.y + (double)rv.z*rv.z + (double)rv.w*rv.w;
        double q2 = (double)qv.x*qv.x + (double)qv.y*qv.y + (double)qv.z*qv.z + (double)qv.w*qv.w;
        double rq = (double)rv.x*qv.x + (double)rv.y*qv.y + (double)rv.z*qv.z + (double)rv.w*qv.w;
        double dxd = (double)qv.x - rv.x, dyd = (double)qv.y - rv.y;
        double dzd = (double)qv.z - rv.z, dwd = (double)qv.w - rv.w;
        double dq = dxd*dxd + dyd*dyd + dzd*dzd + dwd*dwd;
        #pragma unroll
        for (int off = 16; off > 0; off >>= 1) {
            r2 += __shfl_xor_sync(0xffffffffu, r2, off);
            q2 += __shfl_xor_sync(0xffffffffu, q2, off);
            rq += __shfl_xor_sync(0xffffffffu, rq, off);
            dq += __shfl_xor_sync(0xffffffffu, dq, off);
        }
        double ns = sqrt(r2), nt = sqrt(q2);
        double ins = 1.0 / (ns + 1e-12), intq = 1.0 / (nt + 1e-12);
        double ru = r2 * ins;
        double ss2 = r2*ins*ins + 2.0*rq*ins*intq + q2*intq*intq;
        double wn = sqrt(ss2);
        double iw = 1.0 / (wn + 1e-12);
        double rs2 = ru + rq * intq;
        double rw = rs2 * iw;
        double scale = nt * ins;
        float4 qrf;
        {
            double sx = (double)rv.x*ins + (double)qv.x*intq;
            double sy = (double)rv.y*ins + (double)qv.y*intq;
            double sz = (double)rv.z*ins + (double)qv.z*intq;
            double sw = (double)rv.w*ins + (double)qv.w*intq;
            qrf.x = (float)(((double)rv.x - 2.0*rw*(sx*iw) + 2.0*ru*((double)qv.x*intq)) * scale);
            qrf.y = (float)(((double)rv.y - 2.0*rw*(sy*iw) + 2.0*ru*((double)qv.y*intq)) * scale);
            qrf.z = (float)(((double)rv.z - 2.0*rw*(sz*iw) + 2.0*ru*((double)qv.z*intq)) * scale);
            qrf.w = (float)(((double)rv.w - 2.0*rw*(sw*iw) + 2.0*ru*((double)qv.w*intq)) * scale);
        }
        size_t base = (size_t)r * LAT + lane*4;
        if (qi == 0) {
            *(float4*)&g_qout[base] = qrf;
        } else {
            float4 old = *(const float4*)&g_qout[base];
            old.x += qrf.x; old.y += qrf.y; old.z += qrf.z; old.w += qrf.w;
            *(float4*)&g_qout[base] = old;
        }
        if (qi < 3) {
            float4 nr = make_float4(rv.x - qrf.x, rv.y - qrf.y, rv.z - qrf.z, rv.w - qrf.w);
            *(float4*)&g_res[base] = nr;
        }
        if (lane == 0) {
            g_codes[r*NQ + qi] = ix;
            dq_local += dq;
        }
    }
    if (lane == 0) atomicAdd(&g_acc[qi], dq_local);
}

// ---------------- smooth loss ----------------
__global__ void k_smooth() {
    int idx = blockIdx.x * 256 + threadIdx.x;
    int cnt = 0;
    if (idx < BB * (TT - 1)) {
        int b = idx / (TT - 1), t = idx % (TT - 1);
        int a = g_codes[(b*TT + t)*NQ + 0];
        int c = g_codes[(b*TT + t + 1)*NQ + 0];
        cnt = (a != c) ? 1 : 0;
    }
    __shared__ int red[256];
    red[threadIdx.x] = cnt;
    __syncthreads();
    for (int s = 128; s > 0; s >>= 1) {
        if (threadIdx.x < s) red[threadIdx.x] += red[threadIdx.x + s];
        __syncthreads();
    }
    if (threadIdx.x == 0 && red[0]) atomicAdd(&g_acc[4], (double)red[0]);
}

// ---------------- fused decoder (unchanged) ----------------
__global__ __launch_bounds__(256) void k_dec(const float* __restrict__ b1,
                                             const float* __restrict__ b2) {
    extern __shared__ float sm[];
    float* insm = sm;
    float* hsm  = sm + 8*660;
    float* red  = hsm + 8*2560;
    int tid = threadIdx.x;
    int g0 = blockIdx.x * 8;

    for (int e = tid; e < 8*660; e += 256) {
        int ch = e / 660, rem = e % 660;
        int c = rem / 5, l = rem % 5;
        int g = g0 + ch;
        int b = g / COUNT_DEC, n = g % COUNT_DEC;
        int t = n*5 + l;
        float v;
        if (c < 128) v = g_qout[((size_t)b*TT + t)*LAT + c];
        else         v = (float)g_codes[(b*TT + t)*NQ + (c - 128)];
        insm[ch*660 + c*5 + l] = v;
    }
    __syncthreads();

    for (int op = 0; op < 2; op++) {
        int o = tid + op*256;
        float acc[8][5];
        float bbv = b1[o];
        #pragma unroll
        for (int ch = 0; ch < 8; ch++)
            #pragma unroll
            for (int l = 0; l < 5; l++) acc[ch][l] = bbv;
        for (int c = 0; c < 132; c++) {
            float inr[8][5];
            #pragma unroll
            for (int ch = 0; ch < 8; ch++)
                #pragma unroll
                for (int l = 0; l < 5; l++) inr[ch][l] = insm[ch*660 + c*5 + l];
            #pragma unroll
            for (int j = 0; j < 5; j++) {
                float wv = g_w1t[(c*5 + j)*512 + o];
                #pragma unroll
                for (int l = 0; l < 5; l++) {
                    int p = l + j - 2;
                    if (p >= 0 && p < 5) {
                        #pragma unroll
                        for (int ch = 0; ch < 8; ch++) acc[ch][l] += wv * inr[ch][p];
                    }
                }
            }
        }
        #pragma unroll
        for (int ch = 0; ch < 8; ch++)
            #pragma unroll
            for (int l = 0; l < 5; l++)
                hsm[ch*2560 + o*5 + l] = fmaxf(acc[ch][l], 0.f);
    }
    __syncthreads();

    int o2 = tid & 127, gp = tid >> 7;
    float acc2[4][5];
    float bb2 = b2[o2];
    #pragma unroll
    for (int cc = 0; cc < 4; cc++)
        #pragma unroll
        for (int l = 0; l < 5; l++) acc2[cc][l] = bb2;
    for (int c = 0; c < 512; c++) {
        float hr[4][5];
        #pragma unroll
        for (int cc = 0; cc < 4; cc++)
            #pragma unroll
            for (int l = 0; l < 5; l++) hr[cc][l] = hsm[(gp*4 + cc)*2560 + c*5 + l];
        #pragma unroll
        for (int j = 0; j < 3; j++) {
            float wv = g_w2t[(c*3 + j)*128 + o2];
            #pragma unroll
            for (int l = 0; l < 5; l++) {
                int p = l + j - 1;
                if (p >= 0 && p < 5) {
                    #pragma unroll
                    for (int cc = 0; cc < 4; cc++) acc2[cc][l] += wv * hr[cc][p];
                }
            }
        }
    }
    float lsum = 0.f;
    #pragma unroll
    for (int cc = 0; cc < 4; cc++) {
        int g = g0 + gp*4 + cc;
        int b = g / COUNT_DEC, n = g % COUNT_DEC;
        #pragma unroll
        for (int l = 0; l < 5; l++) {
            int t = (n + 1)*5 + l;
            float d = acc2[cc][l] - g_qout[((size_t)b*TT + t)*LAT + o2];
            lsum += d*d;
        }
    }
    red[tid] = lsum;
    __syncthreads();
    for (int s = 128; s > 0; s >>= 1) {
        if (tid < s) red[tid] += red[tid + s];
        __syncthreads();
    }
    if (tid == 0) atomicAdd(&g_acc[5], (double)red[0]);
}

// ---------------- outputs ----------------
__global__ void k_codes_out(float* __restrict__ out, int out_size) {
    int i = blockIdx.x * 256 + threadIdx.x;
    if (i < BB*TT*NQ && i < out_size) out[i] = (float)g_codes[i];
}
__global__ void k_final(float* __restrict__ out, int out_size) {
    if (threadIdx.x != 0 || blockIdx.x != 0) return;
    double nv = (double)BB * TT * LAT;
    double vq = (g_acc[0]/nv + g_acc[1]/nv + g_acc[2]/nv + g_acc[3]/nv) / 4.0;
    double recon = g_acc[5] / ((double)NCHUNKS * LAT * 5);
    double smooth = g_acc[4] / ((double)BB * (TT - 1));
    double loss = recon * 1.0 + vq * 1.0 + smooth * 0.1;
    int base = BB*TT*NQ;
    if (base + 0 < out_size) out[base + 0] = (float)loss;
    if (base + 1 < out_size) out[base + 1] = (float)recon;
    if (base + 2 < out_size) out[base + 2] = (float)vq;
    if (base + 3 < out_size) out[base + 3] = (float)smooth;
}

// ---------------- launch ----------------
extern "C" void kernel_launch(void* const* d_in, const int* in_sizes, int n_in,
                              void* d_out, int out_size) {
    const float* traj = (const float*)d_in[0];
    const float* e1w  = (const float*)d_in[2];
    const float* e1b  = (const float*)d_in[3];
    const float* e2aw = (const float*)d_in[4];
    const float* e2ab = (const float*)d_in[5];
    const float* e2bw = (const float*)d_in[6];
    const float* e2bb = (const float*)d_in[7];
    const float* d1w  = (const float*)d_in[8];
    const float* d1b  = (const float*)d_in[9];
    const float* d2w  = (const float*)d_in[10];
    const float* d2b  = (const float*)d_in[11];
    const float* cb   = (const float*)d_in[12];
    float* out = (float*)d_out;

    const int VQ_SMEM  = 135680;
    const int DEC_SMEM = (8*660 + 8*2560 + 256) * 4;
    const int HM_SMEM  = 45056 + 16*68*4;   // 49,408 B
    const int CB_SMEM  = (2*(8*7*132) + 2*8*40) * 4;
    cudaFuncSetAttribute(k_vq,  cudaFuncAttributeMaxDynamicSharedMemorySize, VQ_SMEM);
    cudaFuncSetAttribute(k_dec, cudaFuncAttributeMaxDynamicSharedMemorySize, DEC_SMEM);
    cudaFuncSetAttribute(k_enc2a_hmma,
                         cudaFuncAttributeMaxDynamicSharedMemorySize, HM_SMEM);
    cudaFuncSetAttribute((const void*)k_conv3<7, false, true, false, 1>,
                         cudaFuncAttributeMaxDynamicSharedMemorySize, CB_SMEM);

    void *p_wh = nullptr, *p_wb = nullptr, *p_z3 = nullptr, *p_ze = nullptr;
    cudaGetSymbolAddress(&p_wh, g_wh);
    cudaGetSymbolAddress(&p_wb, g_wb);
    cudaGetSymbolAddress(&p_z3, g_z3);
    cudaGetSymbolAddress(&p_ze, g_ze);

    k_wprep2<<<(4*32*128*88 + 255)/256, 256>>>(e2aw);                      // 0
    k_enc1<<<dim3(TN/16, BB), 256>>>(traj, e1w, e1b);                      // 1
    k_cbprep<<<(4*8*128*132 + 255)/256, 256>>>(cb);                        // 2
    // enc2a: HMMA bf16 2-limb implicit GEMM                               // 3 <- ncu target
    k_enc2a_hmma<<<dim3(125, 4, BB), 256, HM_SMEM>>>(
        (const __nv_bfloat16*)p_wh, e2ab);
    k_wstage<<<(1*64*8*7*128)/256, 256>>>(e2bw, (float*)p_wb, 7, 1);       // 4
    // enc2b: 512->128, K=7, transposed out (B,T,128), scalar path         // 5
    k_conv3<7, false, true, false, 1><<<dim3(TT/32, 1, BB), 256, CB_SMEM>>>(
        (const float*)p_z3, (const float*)p_wb, e2bb, (float*)p_ze);
    k_zero_acc<<<1, 32>>>();                                               // 6
    k_tw1<<<(512*660 + 255)/256, 256>>>(d1w);                              // 7
    k_tw2<<<(128*1536 + 255)/256, 256>>>(d2w);                             // 8
    k_cbnorm<<<(NQ*KCB)/256, 256>>>(cb);                                   // 9
    for (int qi = 0; qi < NQ; qi++) {
        k_vq<<<(BB*TT)/64, 256, VQ_SMEM>>>(cb, qi);                        // 10-13
    }
    k_smooth<<<(BB*(TT-1) + 255)/256, 256>>>();                            // 14
    k_dec<<<NCHUNKS/8, 256, DEC_SMEM>>>(d1b, d2b);                         // 15
    k_codes_out<<<(BB*TT*NQ)/256, 256>>>(out, out_size);                   // 16
    k_final<<<1, 32>>>(out, out_size);                                     // 17
}

// round 17
// speedup vs baseline: 1.0746x; 1.0746x over previous
#include <cuda_runtime.h>
#include <cuda_bf16.h>
#include <stdint.h>
#include <math.h>

#define BB   16
#define TT   8000
#define TN   800
#define HID  512
#define LAT  128
#define KCB  1024
#define NQ   4
#define COUNT_DEC 1599
#define NCHUNKS   25584   // BB * COUNT_DEC
#define RESCORE_TAU 4e-3f

// ---------------- scratch (device globals; no allocation allowed) ----------------
__device__ float g_z1[BB*HID*TN];        // enc1 out (B,512,800)
__device__ float g_z3[(size_t)BB*HID*TT];// enc2a out (B,512,8000)
__device__ float g_ze[(size_t)BB*TT*LAT];// enc2b out, transposed (B,T,128)
__device__ float g_res[(size_t)BB*TT*LAT];
__device__ float g_qout[(size_t)BB*TT*LAT];
__device__ int   g_codes[BB*TT*NQ];
__device__ float g_cbn[NQ*KCB];
__device__ float g_w1t[132*5*512];       // dec1 weights transposed
__device__ float g_w2t[512*3*128];       // dec2 weights transposed
__device__ float g_wb[1*64*8*7*132];     // enc2b weights pre-staged (scalar conv3)
// enc2a HMMA weight image: per (ocb,chunk): [limb(2)][oc(128)][kpad(88)] bf16
__device__ __nv_bfloat16 g_wh[4*32*22528];
__device__ double g_acc[8];  // [0..3] vq sums, [4] smooth count, [5] recon sum

__device__ __forceinline__ uint32_t pkbf(__nv_bfloat16 x, __nv_bfloat16 y) {
    return (uint32_t)__bfloat16_as_ushort(x) | ((uint32_t)__bfloat16_as_ushort(y) << 16);
}

#define MMA16816(C, A, B0, B1) \
    asm volatile("mma.sync.aligned.m16n8k16.row.col.f32.bf16.bf16.f32 " \
        "{%0,%1,%2,%3}, {%4,%5,%6,%7}, {%8,%9}, {%0,%1,%2,%3};" \
        : "+f"((C)[0]), "+f"((C)[1]), "+f"((C)[2]), "+f"((C)[3]) \
        : "r"((A)[0]), "r"((A)[1]), "r"((A)[2]), "r"((A)[3]), "r"(B0), "r"(B1))

// ---------------- tiny utility kernels ----------------
__global__ void k_zero_acc() {
    if (threadIdx.x < 8) g_acc[threadIdx.x] = 0.0;
}
__global__ void k_tw1(const float* __restrict__ w1) {
    int idx = blockIdx.x * 256 + threadIdx.x;
    if (idx >= 512*660) return;
    int o = idx / 660, r = idx % 660;
    g_w1t[r*512 + o] = w1[idx];
}
__global__ void k_tw2(const float* __restrict__ w2) {
    int idx = blockIdx.x * 256 + threadIdx.x;
    if (idx >= 128*1536) return;
    int o = idx / 1536, r = idx % 1536;
    g_w2t[r*128 + o] = w2[idx];
}
__global__ void k_wstage(const float* __restrict__ wt, float* __restrict__ dst,
                         int K, int OCB) {
    int idx = blockIdx.x * 256 + threadIdx.x;
    int total = OCB * 64 * 8 * K * 128;
    if (idx >= total) return;
    int ol = idx & 127;
    int r  = idx >> 7;
    int j  = r % K;  r /= K;
    int i  = r & 7;  r >>= 3;
    int chunk = r & 63;
    int ocb   = r >> 6;
    dst[((size_t)(ocb*64 + chunk))*(8*K*132) + (i*K + j)*132 + ol] =
        wt[((size_t)(ocb*128 + ol)*512 + chunk*8 + i)*K + j];
}

// enc2a weight prep: im2col k = icl*5 + j (icl in 16-ic chunk), 2 bf16 limbs
__global__ void k_wprep2(const float* __restrict__ wt) {
    int idx = blockIdx.x * 256 + threadIdx.x;
    if (idx >= 4*32*128*88) return;
    int kp = idx % 88; int r = idx / 88;
    int oc = r % 128; r /= 128;
    int ch = r % 32; int ocb = r / 32;
    float w = 0.f;
    if (kp < 80) {
        int icl = kp / 5, j = kp - icl*5;
        w = wt[(((size_t)(ocb*128 + oc))*512 + ch*16 + icl)*5 + j];
    }
    __nv_bfloat16 h = __float2bfloat16(w);
    __nv_bfloat16 l = __float2bfloat16(w - __bfloat162float(h));
    size_t base = (size_t)(ocb*32 + ch)*22528 + (size_t)oc*88 + kp;
    g_wh[base] = h;
    g_wh[base + 11264] = l;
}

// ---------------- enc1: (B,20,800) -> relu conv K=3 -> (B,512,800) ----------------
__global__ __launch_bounds__(256) void k_enc1(const float* __restrict__ traj,
                                              const float* __restrict__ w,
                                              const float* __restrict__ bias) {
    __shared__ float xs[20][18];
    int b = blockIdx.y, t0 = blockIdx.x * 16;
    int tid = threadIdx.x;
    for (int e = tid; e < 20*18; e += 256) {
        int i = e / 18, u = e % 18;
        int tg = t0 + u - 1;
        float v = 0.f;
        if (tg >= 0 && tg < TN) v = traj[((size_t)b*2 + (i/10))*TT + tg*10 + (i%10)];
        xs[i][u] = v;
    }
    __syncthreads();
    int o0 = tid, o1 = tid + 256;
    float acc0[16], acc1[16];
    float b0 = bias[o0], b1v = bias[o1];
    #pragma unroll
    for (int t = 0; t < 16; t++) { acc0[t] = 0.f; acc1[t] = 0.f; }
    for (int i = 0; i < 20; i++) {
        #pragma unroll
        for (int j = 0; j < 3; j++) {
            float w0 = w[(o0*20 + i)*3 + j];
            float w1 = w[(o1*20 + i)*3 + j];
            #pragma unroll
            for (int t = 0; t < 16; t++) {
                float x = xs[i][t + j];
                acc0[t] += w0 * x;
                acc1[t] += w1 * x;
            }
        }
    }
    #pragma unroll
    for (int t = 0; t < 16; t++) {
        g_z1[((size_t)b*HID + o0)*TN + t0 + t] = fmaxf(acc0[t] + b0, 0.f);
        g_z1[((size_t)b*HID + o1)*TN + t0 + t] = fmaxf(acc1[t] + b1v, 0.f);
    }
}

// ---------------- enc2a via mma.sync bf16 2-limb (HMMA) --------------------
// B limbs pre-split into smem bf16 tiles during staging (bit-identical values).
__global__ __launch_bounds__(256) void k_enc2a_hmma(
    const __nv_bfloat16* __restrict__ wh, const float* __restrict__ bias) {
    extern __shared__ char smem[];
    __nv_bfloat16* ash = (__nv_bfloat16*)smem;             // [2][128][88] bf16 = 45056
    __nv_bfloat16* zh  = (__nv_bfloat16*)(smem + 45056);   // [16][68] bf16 = 2176
    __nv_bfloat16* zl  = (__nv_bfloat16*)(smem + 47232);   // [16][68] bf16 = 2176
    int tid = threadIdx.x, lane = tid & 31, warp = tid >> 5;
    int wm = warp & 3, wn = warp >> 2;
    int t0 = blockIdx.x * 64, ob = blockIdx.y * 128, b = blockIdx.z;

    float c[2][4][4];
    #pragma unroll
    for (int i = 0; i < 2; i++)
        #pragma unroll
        for (int nt = 0; nt < 4; nt++)
            #pragma unroll
            for (int q = 0; q < 4; q++) c[i][nt][q] = 0.f;

    uint32_t adst = (uint32_t)__cvta_generic_to_shared(ash);

    for (int ch = 0; ch < 32; ch++) {
        __syncthreads();
        {
            const __nv_bfloat16* src = wh + (size_t)(blockIdx.y*32 + ch) * 22528;
            #pragma unroll
            for (int it = 0; it < 11; it++) {
                int e = tid + it*256;
                asm volatile("cp.async.ca.shared.global [%0], [%1], 16;"
                             :: "r"(adst + e*16), "l"((const void*)(src + e*8)));
            }
            asm volatile("cp.async.commit_group;");
        }
        // z interp staging with inline 2-limb split (identical values to inline path)
        {
            int ic0 = ch * 16;
            for (int e = tid; e < 1088; e += 256) {
                int icl = e / 68, u = e - icl*68;
                int tg = t0 + u - 2;
                float v = 0.f;
                if (tg >= 0 && tg < TT) {
                    const float* row = g_z1 + ((size_t)b*HID + ic0 + icl)*TN;
                    float srcp = fmaxf(((float)tg + 0.5f)*0.5f - 0.5f, 0.0f);
                    int i0 = (int)srcp;
                    int i1 = min(i0 + 1, 3999);
                    float frac = srcp - (float)i0;
                    v = row[i0/5]*(1.0f - frac) + row[i1/5]*frac;
                }
                __nv_bfloat16 h = __float2bfloat16(v);
                __nv_bfloat16 l = __float2bfloat16(v - __bfloat162float(h));
                zh[e] = h;
                zl[e] = l;
            }
        }
        asm volatile("cp.async.wait_group 0;");
        __syncthreads();

        #pragma unroll
        for (int ks = 0; ks < 5; ks++) {
            int kb = ks*16 + (lane & 3)*2;
            uint32_t bL1[4][2], bL2[4][2];
            #pragma unroll
            for (int nt = 0; nt < 4; nt++) {
                int n = wn*32 + nt*8 + (lane >> 2);
                __nv_bfloat16 h[4], l[4];
                #pragma unroll
                for (int q = 0; q < 4; q++) {
                    int kl = kb + (q & 1) + ((q & 2) ? 8 : 0);
                    int icl = kl / 5, j = kl - icl*5;
                    int idx = icl*68 + n + j;
                    h[q] = zh[idx];
                    l[q] = zl[idx];
                }
                bL1[nt][0] = pkbf(h[0], h[1]); bL1[nt][1] = pkbf(h[2], h[3]);
                bL2[nt][0] = pkbf(l[0], l[1]); bL2[nt][1] = pkbf(l[2], l[3]);
            }
            uint32_t aF[2][2][4];
            #pragma unroll
            for (int i = 0; i < 2; i++) {
                int m = wm*32 + i*16 + (lane >> 2);
                #pragma unroll
                for (int lb = 0; lb < 2; lb++) {
                    const __nv_bfloat16* base = ash + lb*11264;
                    aF[i][lb][0] = *(const uint32_t*)(base + (size_t)m*88 + kb);
                    aF[i][lb][1] = *(const uint32_t*)(base + (size_t)(m + 8)*88 + kb);
                    aF[i][lb][2] = *(const uint32_t*)(base + (size_t)m*88 + kb + 8);
                    aF[i][lb][3] = *(const uint32_t*)(base + (size_t)(m + 8)*88 + kb + 8);
                }
            }
            #pragma unroll
            for (int i = 0; i < 2; i++) {
                #pragma unroll
                for (int nt = 0; nt < 4; nt++) {
                    MMA16816(c[i][nt], aF[i][0], bL1[nt][0], bL1[nt][1]);
                    MMA16816(c[i][nt], aF[i][0], bL2[nt][0], bL2[nt][1]);
                    MMA16816(c[i][nt], aF[i][1], bL1[nt][0], bL1[nt][1]);
                }
            }
        }
    }

    #pragma unroll
    for (int i = 0; i < 2; i++) {
        int oc0 = ob + wm*32 + i*16 + (lane >> 2);
        float bv0 = bias[oc0], bv1 = bias[oc0 + 8];
        #pragma unroll
        for (int nt = 0; nt < 4; nt++) {
            int t = t0 + wn*32 + nt*8 + (lane & 3)*2;
            float2 v0, v1;
            v0.x = fmaxf(c[i][nt][0] + bv0, 0.f);
            v0.y = fmaxf(c[i][nt][1] + bv0, 0.f);
            v1.x = fmaxf(c[i][nt][2] + bv1, 0.f);
            v1.y = fmaxf(c[i][nt][3] + bv1, 0.f);
            *(float2*)&g_z3[((size_t)b*HID + oc0)*TT + t]     = v0;
            *(float2*)&g_z3[((size_t)b*HID + oc0 + 8)*TT + t] = v1;
        }
    }
}

// ---------------- conv3 scalar path (enc2b), from R11 ----------------
template<int K, bool RELU, bool TROUT, bool INTERP, int OCB>
__global__ __launch_bounds__(256) void k_conv3(const float* __restrict__ in,
                                               const float* __restrict__ ws,
                                               const float* __restrict__ bias,
                                               float* __restrict__ out) {
    constexpr int P   = (K - 1) / 2;
    constexpr int ZW  = 32 + K - 1;
    constexpr int ZWP = (ZW + 3) & ~3;
    constexpr int WB  = 8 * K * 132;
    constexpr int WB4 = WB / 4;
    constexpr int WITER = (WB4 + 255) / 256;
    constexpr int NZ4 = (K + 6) / 4;
    extern __shared__ float smemf[];
    float* wbuf0 = smemf;
    float* wbuf1 = smemf + WB;
    float* zbuf0 = smemf + 2*WB;
    float* zbuf1 = smemf + 2*WB + 8*ZWP;

    int tid = threadIdx.x;
    int tx = tid & 7, ty = tid >> 3;
    int t0 = blockIdx.x * 32, ob = blockIdx.y * 128, b = blockIdx.z;
    int OCt = OCB * 128;
    int o = ob + ty*4, tt = tx*4;

    float acc[4][4], sum[4][4];
    #pragma unroll
    for (int cIdx = 0; cIdx < 4; cIdx++)
        #pragma unroll
        for (int tl = 0; tl < 4; tl++) { acc[cIdx][tl] = 0.f; sum[cIdx][tl] = 0.f; }

    float zt[2];
    {
        const float* src = ws + ((size_t)(blockIdx.y*64 + 0))*WB;
        uint32_t dst = (uint32_t)__cvta_generic_to_shared(wbuf0);
        #pragma unroll
        for (int it = 0; it < WITER; it++) {
            int e = tid + it*256;
            if (e < WB4)
                asm volatile("cp.async.ca.shared.global [%0], [%1], 16;"
                             :: "r"(dst + e*16), "l"((const void*)(src + e*4)));
        }
        asm volatile("cp.async.commit_group;");
        #pragma unroll
        for (int k = 0; k < 2; k++) {
            int e = tid + k*256;
            float v = 0.f;
            if (e < 8*ZW) {
                int i = e / ZW, u = e - i*ZW;
                int tg = t0 + u - P;
                if (tg >= 0 && tg < TT) {
                    if (INTERP) {
                        const float* row = g_z1 + ((size_t)b*HID + i)*TN;
                        float srcp = fmaxf(((float)tg + 0.5f)*0.5f - 0.5f, 0.0f);
                        int i0 = (int)srcp;
                        int i1 = min(i0 + 1, 3999);
                        float frac = srcp - (float)i0;
                        v = row[i0/5] * (1.0f - frac) + row[i1/5] * frac;
                    } else {
                        v = in[((size_t)b*HID + i)*TT + tg];
                    }
                }
            }
            zt[k] = v;
        }
        asm volatile("cp.async.wait_group 0;");
        #pragma unroll
        for (int k = 0; k < 2; k++) {
            int e = tid + k*256;
            if (e < 8*ZW) { int i = e / ZW, u = e - i*ZW; zbuf0[i*ZWP + u] = zt[k]; }
        }
        __syncthreads();
    }

    for (int c = 0; c < 64; c++) {
        const float* wb_ = (c & 1) ? wbuf1 : wbuf0;
        const float* zb_ = (c & 1) ? zbuf1 : zbuf0;
        float* wbn = (c & 1) ? wbuf0 : wbuf1;
        float* zbn = (c & 1) ? zbuf0 : zbuf1;
        if (c < 63) {
            const float* src = ws + ((size_t)(blockIdx.y*64 + c + 1))*WB;
            uint32_t dst = (uint32_t)__cvta_generic_to_shared(wbn);
            #pragma unroll
            for (int it = 0; it < WITER; it++) {
                int e = tid + it*256;
                if (e < WB4)
                    asm volatile("cp.async.ca.shared.global [%0], [%1], 16;"
                                 :: "r"(dst + e*16), "l"((const void*)(src + e*4)));
            }
            asm volatile("cp.async.commit_group;");
            int ic0 = (c + 1) * 8;
            #pragma unroll
            for (int k = 0; k < 2; k++) {
                int e = tid + k*256;
                float v = 0.f;
                if (e < 8*ZW) {
                    int i = e / ZW, u = e - i*ZW;
                    int tg = t0 + u - P;
                    if (tg >= 0 && tg < TT) {
                        if (INTERP) {
                            const float* row = g_z1 + ((size_t)b*HID + ic0 + i)*TN;
                            float srcp = fmaxf(((float)tg + 0.5f)*0.5f - 0.5f, 0.0f);
                            int i0 = (int)srcp;
                            int i1 = min(i0 + 1, 3999);
                            float frac = srcp - (float)i0;
                            v = row[i0/5] * (1.0f - frac) + row[i1/5] * frac;
                        } else {
                            v = in[((size_t)b*HID + ic0 + i)*TT + tg];
                        }
                    }
                }
                zt[k] = v;
            }
        }
        #pragma unroll
        for (int i = 0; i < 8; i++) {
            float zl2[NZ4 * 4];
            #pragma unroll
            for (int q = 0; q < NZ4; q++)
                *(float4*)&zl2[q*4] = *(const float4*)&zb_[i*ZWP + tt + q*4];
            #pragma unroll
            for (int j = 0; j < K; j++) {
                float4 wv = *(const float4*)&wb_[(i*K + j)*132 + ty*4];
                #pragma unroll
                for (int tl = 0; tl < 4; tl++) {
                    float z = zl2[tl + j];
                    acc[0][tl] += wv.x * z;
                    acc[1][tl] += wv.y * z;
                    acc[2][tl] += wv.z * z;
                    acc[3][tl] += wv.w * z;
                }
            }
        }
        if ((c & 3) == 3) {
            #pragma unroll
            for (int cIdx = 0; cIdx < 4; cIdx++)
                #pragma unroll
                for (int tl = 0; tl < 4; tl++) { sum[cIdx][tl] += acc[cIdx][tl]; acc[cIdx][tl] = 0.f; }
        }
        if (c < 63) {
            asm volatile("cp.async.wait_group 0;");
            #pragma unroll
            for (int k = 0; k < 2; k++) {
                int e = tid + k*256;
                if (e < 8*ZW) { int i = e / ZW, u = e - i*ZW; zbn[i*ZWP + u] = zt[k]; }
            }
        }
        __syncthreads();
    }

    float resv[4][4];
    #pragma unroll
    for (int cIdx = 0; cIdx < 4; cIdx++) {
        float bv = bias[o + cIdx];
        #pragma unroll
        for (int tl = 0; tl < 4; tl++) {
            float v = sum[cIdx][tl] + bv;
            if (RELU) v = fmaxf(v, 0.f);
            resv[cIdx][tl] = v;
        }
    }
    if (!TROUT) {
        #pragma unroll
        for (int cIdx = 0; cIdx < 4; cIdx++) {
            float4 v = make_float4(resv[cIdx][0], resv[cIdx][1], resv[cIdx][2], resv[cIdx][3]);
            *(float4*)&out[((size_t)b*OCt + o + cIdx)*TT + t0 + tt] = v;
        }
    } else {
        #pragma unroll
        for (int tl = 0; tl < 4; tl++) {
            float4 v = make_float4(resv[0][tl], resv[1][tl], resv[2][tl], resv[3][tl]);
            *(float4*)&out[((size_t)b*TT + t0 + tt + tl)*OCt + o] = v;
        }
    }
}

// ---------------- codebook squared norms ----------------
__global__ void k_cbnorm(const float* __restrict__ cb) {
    int id = blockIdx.x * 256 + threadIdx.x;
    if (id >= NQ * KCB) return;
    const float* r = cb + (size_t)id * LAT;
    double s = 0.0;
    for (int d = 0; d < LAT; d++) {
        double v = (double)r[d];
        s += v * v;
    }
    g_cbn[id] = (float)s;
}

// ---------------- residual VQ (R11 scalar version, bit-validated) ----------------
__global__ __launch_bounds__(256) void k_vq(const float* __restrict__ cb_all, int qi) {
    extern __shared__ float sm[];
    float* rsm = sm;
    float* csm = sm + 64*132;
    float* nsm = csm + 128*132;
    int tid = threadIdx.x, lane = tid & 31, w = tid >> 5;
    int row0 = blockIdx.x * 64;
    const float* src = (qi == 0) ? g_ze : g_res;
    for (int e = tid; e < 64*32; e += 256) {
        int lr = e >> 5, d4 = (e & 31) * 4;
        float4 v = *(const float4*)&src[(size_t)(row0 + lr)*LAT + d4];
        *(float4*)&rsm[lr*132 + d4] = v;
    }
    const float* cbq = cb_all + (size_t)qi * KCB * LAT;
    float bestv[8], secv[8]; int besti[8];
    #pragma unroll
    for (int rr = 0; rr < 8; rr++) { bestv[rr] = 3.4e38f; secv[rr] = 3.4e38f; besti[rr] = 0; }

    for (int cc = 0; cc < 8; cc++) {
        __syncthreads();
        for (int e = tid; e < 128*32; e += 256) {
            int k = e >> 5, d4 = (e & 31) * 4;
            float4 v = *(const float4*)&cbq[(size_t)(cc*128 + k)*LAT + d4];
            *(float4*)&csm[k*132 + d4] = v;
        }
        if (tid < 128) nsm[tid] = g_cbn[qi*KCB + cc*128 + tid];
        __syncthreads();
        float acc[8][4];
        #pragma unroll
        for (int rr = 0; rr < 8; rr++)
            #pragma unroll
            for (int c = 0; c < 4; c++) acc[rr][c] = 0.f;
        #pragma unroll 2
        for (int d = 0; d < 128; d += 4) {
            float4 cv[4];
            #pragma unroll
            for (int c = 0; c < 4; c++) cv[c] = *(const float4*)&csm[(lane*4 + c)*132 + d];
            #pragma unroll
            for (int rr = 0; rr < 8; rr++) {
                float4 rv = *(const float4*)&rsm[(w*8 + rr)*132 + d];
                #pragma unroll
                for (int c = 0; c < 4; c++) {
                    acc[rr][c] += rv.x*cv[c].x + rv.y*cv[c].y + rv.z*cv[c].z + rv.w*cv[c].w;
                }
            }
        }
        #pragma unroll
        for (int rr = 0; rr < 8; rr++) {
            #pragma unroll
            for (int c = 0; c < 4; c++) {
                float dist = nsm[lane*4 + c] - 2.0f * acc[rr][c];
                int idx = cc*128 + lane*4 + c;
                if (dist < bestv[rr]) { secv[rr] = bestv[rr]; bestv[rr] = dist; besti[rr] = idx; }
                else if (dist < secv[rr]) { secv[rr] = dist; }
            }
        }
    }

    double dq_local = 0.0;
    for (int rr = 0; rr < 8; rr++) {
        float v1 = bestv[rr]; int i1 = besti[rr]; float v2 = secv[rr];
        #pragma unroll
        for (int off = 16; off > 0; off >>= 1) {
            float ov1 = __shfl_xor_sync(0xffffffffu, v1, off);
            int   oi1 = __shfl_xor_sync(0xffffffffu, i1, off);
            float ov2 = __shfl_xor_sync(0xffffffffu, v2, off);
            if (ov1 < v1 || (ov1 == v1 && oi1 < i1)) {
                v2 = fminf(v1, ov2);
                v1 = ov1; i1 = oi1;
            } else {
                v2 = fminf(v2, ov1);
            }
        }
        int ix = i1;
        int rloc = w*8 + rr;
        if (v2 - v1 < RESCORE_TAU) {
            double bd = 1e300; int bi = 0x7fffffff;
            for (int kk = 0; kk < 32; kk++) {
                int k = kk*32 + lane;
                const float* cr = cbq + (size_t)k * LAT;
                double s = 0.0;
                for (int d = 0; d < 128; d++) {
                    double cd = (double)cr[d];
                    double rd = (double)rsm[rloc*132 + d];
                    s += cd*cd - 2.0*rd*cd;
                }
                if (s < bd || (s == bd && k < bi)) { bd = s; bi = k; }
            }
            #pragma unroll
            for (int off = 16; off > 0; off >>= 1) {
                double ob = __shfl_xor_sync(0xffffffffu, bd, off);
                int    oi = __shfl_xor_sync(0xffffffffu, bi, off);
                if (ob < bd || (ob == bd && oi < bi)) { bd = ob; bi = oi; }
            }
            ix = bi;
        }

        int r = row0 + rloc;
        const float* q = cbq + (size_t)ix * LAT;
        float4 qv = *(const float4*)&q[lane*4];
        float4 rv = *(const float4*)&rsm[rloc*132 + lane*4];
        double r2 = (double)rv.x*rv.x + (double)rv.y*rv.y + (double)rv.z*rv.z + (double)rv.w*rv.w;
        double q2 = (double)qv.x*qv.x + (double)qv.y*qv.y + (double)qv.z*qv.z + (double)qv.w*qv.w;
        double rq = (double)rv.x*qv.x + (double)rv.y*qv.y + (double)rv.z*qv.z + (double)rv.w*qv.w;
        double dxd = (double)qv.x - rv.x, dyd = (double)qv.y - rv.y;
        double dzd = (double)qv.z - rv.z, dwd = (double)qv.w - rv.w;
        double dq = dxd*dxd + dyd*dyd + dzd*dzd + dwd*dwd;
        #pragma unroll
        for (int off = 16; off > 0; off >>= 1) {
            r2 += __shfl_xor_sync(0xffffffffu, r2, off);
            q2 += __shfl_xor_sync(0xffffffffu, q2, off);
            rq += __shfl_xor_sync(0xffffffffu, rq, off);
            dq += __shfl_xor_sync(0xffffffffu, dq, off);
        }
        double ns = sqrt(r2), nt = sqrt(q2);
        double ins = 1.0 / (ns + 1e-12), intq = 1.0 / (nt + 1e-12);
        double ru = r2 * ins;
        double ss2 = r2*ins*ins + 2.0*rq*ins*intq + q2*intq*intq;
        double wn = sqrt(ss2);
        double iw = 1.0 / (wn + 1e-12);
        double rs = ru + rq * intq;
        double rw = rs * iw;
        double scale = nt * ins;
        float4 qrf;
        {
            double sx = (double)rv.x*ins + (double)qv.x*intq;
            double sy = (double)rv.y*ins + (double)qv.y*intq;
            double sz = (double)rv.z*ins + (double)qv.z*intq;
            double sw = (double)rv.w*ins + (double)qv.w*intq;
            qrf.x = (float)(((double)rv.x - 2.0*rw*(sx*iw) + 2.0*ru*((double)qv.x*intq)) * scale);
            qrf.y = (float)(((double)rv.y - 2.0*rw*(sy*iw) + 2.0*ru*((double)qv.y*intq)) * scale);
            qrf.z = (float)(((double)rv.z - 2.0*rw*(sz*iw) + 2.0*ru*((double)qv.z*intq)) * scale);
            qrf.w = (float)(((double)rv.w - 2.0*rw*(sw*iw) + 2.0*ru*((double)qv.w*intq)) * scale);
        }
        size_t base = (size_t)r * LAT + lane*4;
        if (qi == 0) {
            *(float4*)&g_qout[base] = qrf;
        } else {
            float4 old = *(const float4*)&g_qout[base];
            old.x += qrf.x; old.y += qrf.y; old.z += qrf.z; old.w += qrf.w;
            *(float4*)&g_qout[base] = old;
        }
        if (qi < 3) {
            float4 nr = make_float4(rv.x - qrf.x, rv.y - qrf.y, rv.z - qrf.z, rv.w - qrf.w);
            *(float4*)&g_res[base] = nr;
        }
        if (lane == 0) {
            g_codes[r*NQ + qi] = ix;
            dq_local += dq;
        }
    }
    if (lane == 0) atomicAdd(&g_acc[qi], dq_local);
}

// ---------------- smooth loss ----------------
__global__ void k_smooth() {
    int idx = blockIdx.x * 256 + threadIdx.x;
    int cnt = 0;
    if (idx < BB * (TT - 1)) {
        int b = idx / (TT - 1), t = idx % (TT - 1);
        int a = g_codes[(b*TT + t)*NQ + 0];
        int c = g_codes[(b*TT + t + 1)*NQ + 0];
        cnt = (a != c) ? 1 : 0;
    }
    __shared__ int red[256];
    red[threadIdx.x] = cnt;
    __syncthreads();
    for (int s = 128; s > 0; s >>= 1) {
        if (threadIdx.x < s) red[threadIdx.x] += red[threadIdx.x + s];
        __syncthreads();
    }
    if (threadIdx.x == 0 && red[0]) atomicAdd(&g_acc[4], (double)red[0]);
}

// ---------------- fused decoder (unchanged) ----------------
__global__ __launch_bounds__(256) void k_dec(const float* __restrict__ b1,
                                             const float* __restrict__ b2) {
    extern __shared__ float sm[];
    float* insm = sm;
    float* hsm  = sm + 8*660;
    float* red  = hsm + 8*2560;
    int tid = threadIdx.x;
    int g0 = blockIdx.x * 8;

    for (int e = tid; e < 8*660; e += 256) {
        int ch = e / 660, rem = e % 660;
        int c = rem / 5, l = rem % 5;
        int g = g0 + ch;
        int b = g / COUNT_DEC, n = g % COUNT_DEC;
        int t = n*5 + l;
        float v;
        if (c < 128) v = g_qout[((size_t)b*TT + t)*LAT + c];
        else         v = (float)g_codes[(b*TT + t)*NQ + (c - 128)];
        insm[ch*660 + c*5 + l] = v;
    }
    __syncthreads();

    for (int op = 0; op < 2; op++) {
        int o = tid + op*256;
        float acc[8][5];
        float bbv = b1[o];
        #pragma unroll
        for (int ch = 0; ch < 8; ch++)
            #pragma unroll
            for (int l = 0; l < 5; l++) acc[ch][l] = bbv;
        for (int c = 0; c < 132; c++) {
            float inr[8][5];
            #pragma unroll
            for (int ch = 0; ch < 8; ch++)
                #pragma unroll
                for (int l = 0; l < 5; l++) inr[ch][l] = insm[ch*660 + c*5 + l];
            #pragma unroll
            for (int j = 0; j < 5; j++) {
                float wv = g_w1t[(c*5 + j)*512 + o];
                #pragma unroll
                for (int l = 0; l < 5; l++) {
                    int p = l + j - 2;
                    if (p >= 0 && p < 5) {
                        #pragma unroll
                        for (int ch = 0; ch < 8; ch++) acc[ch][l] += wv * inr[ch][p];
                    }
                }
            }
        }
        #pragma unroll
        for (int ch = 0; ch < 8; ch++)
            #pragma unroll
            for (int l = 0; l < 5; l++)
                hsm[ch*2560 + o*5 + l] = fmaxf(acc[ch][l], 0.f);
    }
    __syncthreads();

    int o2 = tid & 127, gp = tid >> 7;
    float acc2[4][5];
    float bb2 = b2[o2];
    #pragma unroll
    for (int cc = 0; cc < 4; cc++)
        #pragma unroll
        for (int l = 0; l < 5; l++) acc2[cc][l] = bb2;
    for (int c = 0; c < 512; c++) {
        float hr[4][5];
        #pragma unroll
        for (int cc = 0; cc < 4; cc++)
            #pragma unroll
            for (int l = 0; l < 5; l++) hr[cc][l] = hsm[(gp*4 + cc)*2560 + c*5 + l];
        #pragma unroll
        for (int j = 0; j < 3; j++) {
            float wv = g_w2t[(c*3 + j)*128 + o2];
            #pragma unroll
            for (int l = 0; l < 5; l++) {
                int p = l + j - 1;
                if (p >= 0 && p < 5) {
                    #pragma unroll
                    for (int cc = 0; cc < 4; cc++) acc2[cc][l] += wv * hr[cc][p];
                }
            }
        }
    }
    float lsum = 0.f;
    #pragma unroll
    for (int cc = 0; cc < 4; cc++) {
        int g = g0 + gp*4 + cc;
        int b = g / COUNT_DEC, n = g % COUNT_DEC;
        #pragma unroll
        for (int l = 0; l < 5; l++) {
            int t = (n + 1)*5 + l;
            float d = acc2[cc][l] - g_qout[((size_t)b*TT + t)*LAT + o2];
            lsum += d*d;
        }
    }
    red[tid] = lsum;
    __syncthreads();
    for (int s = 128; s > 0; s >>= 1) {
        if (tid < s) red[tid] += red[tid + s];
        __syncthreads();
    }
    if (tid == 0) atomicAdd(&g_acc[5], (double)red[0]);
}

// ---------------- outputs ----------------
__global__ void k_codes_out(float* __restrict__ out, int out_size) {
    int i = blockIdx.x * 256 + threadIdx.x;
    if (i < BB*TT*NQ && i < out_size) out[i] = (float)g_codes[i];
}
__global__ void k_final(float* __restrict__ out, int out_size) {
    if (threadIdx.x != 0 || blockIdx.x != 0) return;
    double nv = (double)BB * TT * LAT;
    double vq = (g_acc[0]/nv + g_acc[1]/nv + g_acc[2]/nv + g_acc[3]/nv) / 4.0;
    double recon = g_acc[5] / ((double)NCHUNKS * LAT * 5);
    double smooth = g_acc[4] / ((double)BB * (TT - 1));
    double loss = recon * 1.0 + vq * 1.0 + smooth * 0.1;
    int base = BB*TT*NQ;
    if (base + 0 < out_size) out[base + 0] = (float)loss;
    if (base + 1 < out_size) out[base + 1] = (float)recon;
    if (base + 2 < out_size) out[base + 2] = (float)vq;
    if (base + 3 < out_size) out[base + 3] = (float)smooth;
}

// ---------------- launch (index 3 = k_enc2a_hmma for ncu) ----------------
extern "C" void kernel_launch(void* const* d_in, const int* in_sizes, int n_in,
                              void* d_out, int out_size) {
    const float* traj = (const float*)d_in[0];
    const float* e1w  = (const float*)d_in[2];
    const float* e1b  = (const float*)d_in[3];
    const float* e2aw = (const float*)d_in[4];
    const float* e2ab = (const float*)d_in[5];
    const float* e2bw = (const float*)d_in[6];
    const float* e2bb = (const float*)d_in[7];
    const float* d1w  = (const float*)d_in[8];
    const float* d1b  = (const float*)d_in[9];
    const float* d2w  = (const float*)d_in[10];
    const float* d2b  = (const float*)d_in[11];
    const float* cb   = (const float*)d_in[12];
    float* out = (float*)d_out;

    const int VQ_SMEM  = (64*132 + 128*132 + 128) * 4;   // 101,888 B
    const int DEC_SMEM = (8*660 + 8*2560 + 256) * 4;
    const int HM_SMEM  = 45056 + 2176 + 2176;            // 49,408 B
    const int CB_SMEM  = (2*(8*7*132) + 2*8*40) * 4;
    cudaFuncSetAttribute(k_vq,  cudaFuncAttributeMaxDynamicSharedMemorySize, VQ_SMEM);
    cudaFuncSetAttribute(k_dec, cudaFuncAttributeMaxDynamicSharedMemorySize, DEC_SMEM);
    cudaFuncSetAttribute(k_enc2a_hmma,
                         cudaFuncAttributeMaxDynamicSharedMemorySize, HM_SMEM);
    cudaFuncSetAttribute((const void*)k_conv3<7, false, true, false, 1>,
                         cudaFuncAttributeMaxDynamicSharedMemorySize, CB_SMEM);

    void *p_wh = nullptr, *p_wb = nullptr, *p_z3 = nullptr, *p_ze = nullptr;
    cudaGetSymbolAddress(&p_wh, g_wh);
    cudaGetSymbolAddress(&p_wb, g_wb);
    cudaGetSymbolAddress(&p_z3, g_z3);
    cudaGetSymbolAddress(&p_ze, g_ze);

    k_wprep2<<<(4*32*128*88 + 255)/256, 256>>>(e2aw);                      // 0
    k_enc1<<<dim3(TN/16, BB), 256>>>(traj, e1w, e1b);                      // 1
    k_wstage<<<(1*64*8*7*128)/256, 256>>>(e2bw, (float*)p_wb, 7, 1);       // 2
    // enc2a: HMMA bf16 2-limb, staged B limbs                             // 3 <- ncu target
    k_enc2a_hmma<<<dim3(125, 4, BB), 256, HM_SMEM>>>(
        (const __nv_bfloat16*)p_wh, e2ab);
    // enc2b: 512->128, K=7, transposed out (B,T,128), scalar path         // 4
    k_conv3<7, false, true, false, 1><<<dim3(TT/32, 1, BB), 256, CB_SMEM>>>(
        (const float*)p_z3, (const float*)p_wb, e2bb, (float*)p_ze);
    k_zero_acc<<<1, 32>>>();                                               // 5
    k_tw1<<<(512*660 + 255)/256, 256>>>(d1w);                              // 6
    k_tw2<<<(128*1536 + 255)/256, 256>>>(d2w);                             // 7
    k_cbnorm<<<(NQ*KCB)/256, 256>>>(cb);                                   // 8
    for (int qi = 0; qi < NQ; qi++) {
        k_vq<<<(BB*TT)/64, 256, VQ_SMEM>>>(cb, qi);                        // 9-12
    }
    k_smooth<<<(BB*(TT-1) + 255)/256, 256>>>();                            // 13
    k_dec<<<NCHUNKS/8, 256, DEC_SMEM>>>(d1b, d2b);                         // 14
    k_codes_out<<<(BB*TT*NQ)/256, 256>>>(out, out_size);                   // 15
    k_final<<<1, 32>>>(out, out_size);                                     // 16
}